// round 14
// baseline (speedup 1.0000x reference)
#include <cuda_runtime.h>
#include <math.h>
#include <stdint.h>
#include <float.h>

#define BSZ 8
#define TT  8192
#define FF  1024
#define HH  256
#define OO  2
#define MTOK (BSZ * TT)   // 65536 tokens
#define NCHUNK 64

// ---- scratch (static device globals; no runtime allocation) ----
__device__ uint4  g_hb4[(size_t)MTOK * 32];   // 32 MB bf16 h, layout [mblk 512][kp 128][m 128]
__device__ float  g_logit[MTOK];
__device__ float2 g_stat[BSZ];
__device__ float  g_part[BSZ * NCHUNK * HH];
__device__ uint4  g_w1s[64 * 512];            // 512 KB: W1 bf16 [kt 64][kp 8][n 256]
__device__ uint4  g_wvs[16 * 512];            // 128 KB: Wv bf16 [blk=nb*4+kh][kp 32][n 64]
__device__ uint4  g_wus[16 * 512];            // 128 KB: Wu

// ---- helpers ----
__device__ __forceinline__ uint32_t pbf(float lo, float hi) {
    uint32_t r; asm("cvt.rn.bf16x2.f32 %0, %1, %2;" : "=r"(r) : "f"(hi), "f"(lo)); return r;
}
__device__ __forceinline__ float tanhfast(float x) {
    float y; asm("tanh.approx.f32 %0, %1;" : "=f"(y) : "f"(x)); return y;
}
__device__ __forceinline__ void mma16(float4& d, const uint32_t* a, uint32_t b0, uint32_t b1) {
    asm volatile("mma.sync.aligned.m16n8k16.row.col.f32.bf16.bf16.f32 "
        "{%0,%1,%2,%3}, {%4,%5,%6,%7}, {%8,%9}, {%0,%1,%2,%3};"
        : "+f"(d.x), "+f"(d.y), "+f"(d.z), "+f"(d.w)
        : "r"(a[0]), "r"(a[1]), "r"(a[2]), "r"(a[3]), "r"(b0), "r"(b1));
}
__device__ __forceinline__ uint32_t s2u(const void* p) {
    uint32_t a; asm("{ .reg .u64 t; cvta.to.shared.u64 t, %1; cvt.u32.u64 %0, t; }" : "=r"(a) : "l"(p));
    return a;
}
__device__ __forceinline__ void cpa16(uint32_t dst, const void* src) {
    asm volatile("cp.async.cg.shared.global [%0], [%1], 16;" :: "r"(dst), "l"(src));
}
__device__ __forceinline__ void cp_commit() { asm volatile("cp.async.commit_group;"); }
__device__ __forceinline__ void cp_wait0()  { asm volatile("cp.async.wait_group 0;"); }
__device__ __forceinline__ void cp_wait1()  { asm volatile("cp.async.wait_group 1;"); }
__device__ __forceinline__ void cp_wait2()  { asm volatile("cp.async.wait_group 2;"); }

// ============================================================================
// kpre: merged weight pre-conversion (proven).
//  blocks 0..63  : W1 -> g_w1s [kt 64][kp 8][n 256]
//  blocks 64..79 : Wv/Wu -> g_wvs/g_wus [blk 16][kp 32][n 64]
// ============================================================================
__global__ __launch_bounds__(256)
void kpre(const float* __restrict__ W1, const float* __restrict__ Wv,
          const float* __restrict__ Wu)
{
    const int tid = threadIdx.x;
    if (blockIdx.x < 64) {
        const int kt = blockIdx.x;
        const int kp = tid >> 5, n8 = (tid & 31) << 3;
        const float* r0 = W1 + (size_t)(kt * 16 + 2 * kp) * HH + n8;
        const float4 a0 = *(const float4*)(r0),        a1 = *(const float4*)(r0 + 4);
        const float4 b0 = *(const float4*)(r0 + HH),   b1 = *(const float4*)(r0 + HH + 4);
        g_w1s[kt * 512 + kp * 64 + (n8 >> 2)] =
            make_uint4(pbf(a0.x, b0.x), pbf(a0.y, b0.y), pbf(a0.z, b0.z), pbf(a0.w, b0.w));
        g_w1s[kt * 512 + kp * 64 + (n8 >> 2) + 1] =
            make_uint4(pbf(a1.x, b1.x), pbf(a1.y, b1.y), pbf(a1.z, b1.z), pbf(a1.w, b1.w));
    } else {
        const int blk = blockIdx.x - 64;
        const int nb = blk >> 2, kh = blk & 3;
        const int kp = tid >> 3, n8 = (tid & 7) << 3;
        const size_t off = (size_t)(kh * 64 + 2 * kp) * HH + nb * 64 + n8;
        {
            const float4 a0 = *(const float4*)(Wv + off),      a1 = *(const float4*)(Wv + off + 4);
            const float4 b0 = *(const float4*)(Wv + off + HH), b1 = *(const float4*)(Wv + off + HH + 4);
            g_wvs[blk * 512 + kp * 16 + (n8 >> 2)] =
                make_uint4(pbf(a0.x, b0.x), pbf(a0.y, b0.y), pbf(a0.z, b0.z), pbf(a0.w, b0.w));
            g_wvs[blk * 512 + kp * 16 + (n8 >> 2) + 1] =
                make_uint4(pbf(a1.x, b1.x), pbf(a1.y, b1.y), pbf(a1.z, b1.z), pbf(a1.w, b1.w));
        }
        {
            const float4 a0 = *(const float4*)(Wu + off),      a1 = *(const float4*)(Wu + off + 4);
            const float4 b0 = *(const float4*)(Wu + off + HH), b1 = *(const float4*)(Wu + off + HH + 4);
            g_wus[blk * 512 + kp * 16 + (n8 >> 2)] =
                make_uint4(pbf(a0.x, b0.x), pbf(a0.y, b0.y), pbf(a0.z, b0.z), pbf(a0.w, b0.w));
            g_wus[blk * 512 + kp * 16 + (n8 >> 2) + 1] =
                make_uint4(pbf(a1.x, b1.x), pbf(a1.y, b1.y), pbf(a1.z, b1.z), pbf(a1.w, b1.w));
        }
    }
}

// ============================================================================
// K12: FUSED h-GEMM + gates. CTA = 128 tokens, 512 thr.
// Phase 1 (R10-proven): h = relu(bags@W1+b1), K=32 stages, 4-slot cp.async;
//   epilogue -> h bf16 into resident smem As2 [kp 128][136] + g_hb4 (for K3b).
// Phase 2 (R11-proven indexing): dual gates GEMM from As2, 8 B-stages
//   (2 n-passes x 4 k-quarters) double-buffered; logits -> g_logit.
// ============================================================================
#define K1_ASLOT (128 * 36)     // 4608 raw A words / slot
#define K1_BSLOT (16 * 264)     // 4224 B words / slot
#define K1_FBUF  (16 * 136)     // 2176 bf16 A words / buffer
#define F_SMEM   ((4 * K1_ASLOT + 4 * K1_BSLOT + 2 * K1_FBUF) * 4)   // 158720 B
#define P2_BSLOT (32 * 136)     // 4352 words per phase-2 B stage
__global__ __launch_bounds__(512, 1)
void k12_fused(const float* __restrict__ A, const float* __restrict__ bias,
               const float* __restrict__ bv, const float* __restrict__ bu,
               const float* __restrict__ ww, const float* __restrict__ bw,
               const unsigned char* __restrict__ mask)
{
    extern __shared__ uint32_t sm1[];
    // phase-1 layout
    uint32_t* Araw = sm1;                       // [4][128][36] raw fp32
    uint32_t* Bst  = sm1 + 4 * K1_ASLOT;        // [4][16][264]
    uint32_t* bfA  = Bst + 4 * K1_BSLOT;        // [2][16][136]
    // phase-2 layout (reuses the same allocation after phase 1 completes)
    uint32_t* As2  = sm1;                       // [128 kp][136]
    uint32_t* BV2  = sm1 + 128 * 136;           // [2][32][136]
    uint32_t* BU2  = BV2 + 2 * P2_BSLOT;
    __shared__ float red[4][128];
    const uint32_t sAraw = s2u(Araw), sBst = s2u(Bst);
    const uint32_t sBV2 = s2u(BV2), sBU2 = s2u(BU2);

    const int tid = threadIdx.x;
    const int lane = tid & 31, wid = tid >> 5;
    const int wm = wid & 3, wn = wid >> 2;       // both phases: 4x4 warp grid
    const int g = lane >> 2, tg = lane & 3;
    const size_t mBase = (size_t)blockIdx.x * 128;

    // ---------------- phase 1: h = relu(bags @ W1 + b1) ----------------
    const int ar = tid >> 2, aq = tid & 3;       // A: row, 8k-quarter
    const float* aSrc = A + (mBase + ar) * FF + aq * 8;

    auto issue = [&](int kt2) {
        const int slot = kt2 & 3;
        const uint32_t aw = sAraw + (slot * K1_ASLOT + ar * 36 + aq * 8) * 4;
        cpa16(aw,      aSrc + kt2 * 32);
        cpa16(aw + 16, aSrc + kt2 * 32 + 4);
        const uint32_t bw_ = sBst + slot * (K1_BSLOT * 4);
        cpa16(bw_ + ((tid >> 6) * 264 + (tid & 63) * 4) * 4,
              (const char*)g_w1s + (size_t)(2 * kt2) * 8192 + (size_t)tid * 16);
        cpa16(bw_ + ((8 + (tid >> 6)) * 264 + (tid & 63) * 4) * 4,
              (const char*)g_w1s + (size_t)(2 * kt2 + 1) * 8192 + (size_t)tid * 16);
        cp_commit();
    };
    issue(0); issue(1); issue(2);

    float4 acc[2][8];
    #pragma unroll
    for (int i = 0; i < 2; i++)
        #pragma unroll
        for (int j = 0; j < 8; j++) acc[i][j] = make_float4(0.f, 0.f, 0.f, 0.f);

    for (int kt2 = 0; kt2 < 32; kt2++) {
        if (kt2 <= 29) cp_wait2();
        else if (kt2 == 30) cp_wait1();
        else cp_wait0();

        const int slot = kt2 & 3;
        {
            const uint32_t* rw = Araw + slot * K1_ASLOT + ar * 36 + aq * 8;
            const float4 v0 = *(const float4*)rw;
            const float4 v1 = *(const float4*)(rw + 4);
            uint32_t* bf = bfA + (kt2 & 1) * K1_FBUF;
            bf[(aq * 4 + 0) * 136 + ar] = pbf(v0.x, v0.y);
            bf[(aq * 4 + 1) * 136 + ar] = pbf(v0.z, v0.w);
            bf[(aq * 4 + 2) * 136 + ar] = pbf(v1.x, v1.y);
            bf[(aq * 4 + 3) * 136 + ar] = pbf(v1.z, v1.w);
        }
        __syncthreads();     // publish stage; proves slot (kt2-1)%4 drained
        if (kt2 + 3 < 32) issue(kt2 + 3);

        const uint32_t* ap = bfA + (kt2 & 1) * K1_FBUF;
        const uint32_t* bp = Bst + slot * K1_BSLOT;
        #pragma unroll
        for (int s = 0; s < 2; s++) {
            const int r0 = s * 8 + tg, r1 = s * 8 + tg + 4;
            uint32_t afr[2][4];
            #pragma unroll
            for (int fm = 0; fm < 2; fm++) {
                const int m = wm * 32 + fm * 16 + g;
                afr[fm][0] = ap[r0 * 136 + m];  afr[fm][1] = ap[r0 * 136 + m + 8];
                afr[fm][2] = ap[r1 * 136 + m];  afr[fm][3] = ap[r1 * 136 + m + 8];
            }
            #pragma unroll
            for (int fn = 0; fn < 8; fn++) {
                const int n = wn * 64 + fn * 8 + g;
                const uint32_t b0 = bp[r0 * 264 + n], b1 = bp[r1 * 264 + n];
                mma16(acc[0][fn], afr[0], b0, b1);
                mma16(acc[1][fn], afr[1], b0, b1);
            }
        }
    }
    __syncthreads();   // all phase-1 smem reads done before As2 overwrite

    // ---- phase-1 epilogue: bias+relu -> As2 (smem, [kp][136]) + g_hb4 ----
    uint32_t* hbw = (uint32_t*)g_hb4 + (size_t)blockIdx.x * 16384;
    #pragma unroll
    for (int fm = 0; fm < 2; fm++) {
        #pragma unroll
        for (int half = 0; half < 2; half++) {
            const int mloc = wm * 32 + fm * 16 + g + half * 8;
            #pragma unroll
            for (int fn = 0; fn < 8; fn++) {
                const int c = wn * 64 + fn * 8 + tg * 2;
                const float v0 = half ? acc[fm][fn].z : acc[fm][fn].x;
                const float v1 = half ? acc[fm][fn].w : acc[fm][fn].y;
                const float h0 = fmaxf(v0 + bias[c], 0.f);
                const float h1 = fmaxf(v1 + bias[c + 1], 0.f);
                const uint32_t hw = pbf(h0, h1);
                As2[(c >> 1) * 136 + mloc] = hw;
                hbw[(c >> 1) * 128 + mloc] = hw;
            }
        }
    }
    __syncthreads();   // As2 complete before phase-2 MMAs

    // ---------------- phase 2: gated-attention logits ----------------
    auto fill2 = [&](int s2, int pb) {
        const int p = s2 >> 2, kh = s2 & 3;
        #pragma unroll
        for (int j = 0; j < 2; j++) {
            const int c = tid * 2 + j;                 // 0..1023
            const int q = c >> 9, cc = c & 511;
            const int kp = cc >> 4, nw = (cc & 15) * 4;
            const int blk = (2 * p + q) * 4 + kh;
            const uint32_t d = (pb * P2_BSLOT + kp * 136 + q * 64 + nw) * 4;
            cpa16(sBV2 + d, (const char*)g_wvs + (size_t)blk * 8192 + (size_t)cc * 16);
            cpa16(sBU2 + d, (const char*)g_wus + (size_t)blk * 8192 + (size_t)cc * 16);
        }
        cp_commit();
    };
    fill2(0, 0);

    float rowsum[4] = {0.f, 0.f, 0.f, 0.f};
    float4 accV[2][4], accU[2][4];

    for (int s2 = 0; s2 < 8; s2++) {
        const int pb = s2 & 1, p = s2 >> 2, kh = s2 & 3;
        if (s2 < 7) { fill2(s2 + 1, pb ^ 1); cp_wait1(); }
        else cp_wait0();
        __syncthreads();

        if (kh == 0) {
            #pragma unroll
            for (int i = 0; i < 2; i++)
                #pragma unroll
                for (int j = 0; j < 4; j++) {
                    accV[i][j] = make_float4(0.f, 0.f, 0.f, 0.f);
                    accU[i][j] = make_float4(0.f, 0.f, 0.f, 0.f);
                }
        }

        const uint32_t* vp = BV2 + pb * P2_BSLOT;
        const uint32_t* up = BU2 + pb * P2_BSLOT;
        #pragma unroll
        for (int ks = 0; ks < 4; ks++) {
            const int r = ks * 8 + tg;
            const int ra = kh * 32 + r;
            uint32_t afr[2][4];
            #pragma unroll
            for (int fm = 0; fm < 2; fm++) {
                const int m = wm * 32 + fm * 16 + g;
                afr[fm][0] = As2[ra * 136 + m];       afr[fm][1] = As2[ra * 136 + m + 8];
                afr[fm][2] = As2[(ra + 4) * 136 + m]; afr[fm][3] = As2[(ra + 4) * 136 + m + 8];
            }
            #pragma unroll
            for (int fn = 0; fn < 4; fn++) {
                const int n = wn * 32 + fn * 8 + g;
                const uint32_t v0 = vp[r * 136 + n], v1 = vp[(r + 4) * 136 + n];
                const uint32_t u0 = up[r * 136 + n], u1 = up[(r + 4) * 136 + n];
                mma16(accV[0][fn], afr[0], v0, v1);
                mma16(accV[1][fn], afr[1], v0, v1);
                mma16(accU[0][fn], afr[0], u0, u1);
                mma16(accU[1][fn], afr[1], u0, u1);
            }
        }

        if (kh == 3) {
            #pragma unroll
            for (int fm = 0; fm < 2; fm++) {
                #pragma unroll
                for (int fn = 0; fn < 4; fn++) {
                    const int c = p * 128 + wn * 32 + fn * 8 + tg * 2;
                    const float bv0 = bv[c], bv1 = bv[c + 1];
                    const float bu0 = bu[c], bu1 = bu[c + 1];
                    const float w0 = ww[c],  w1 = ww[c + 1];
                    const float4 av = accV[fm][fn], au = accU[fm][fn];
                    float v, u;
                    v = tanhfast(av.x + bv0); u = 0.5f * tanhfast(0.5f * (au.x + bu0)) + 0.5f;
                    rowsum[fm * 2 + 0] = fmaf(v * u, w0, rowsum[fm * 2 + 0]);
                    v = tanhfast(av.y + bv1); u = 0.5f * tanhfast(0.5f * (au.y + bu1)) + 0.5f;
                    rowsum[fm * 2 + 0] = fmaf(v * u, w1, rowsum[fm * 2 + 0]);
                    v = tanhfast(av.z + bv0); u = 0.5f * tanhfast(0.5f * (au.z + bu0)) + 0.5f;
                    rowsum[fm * 2 + 1] = fmaf(v * u, w0, rowsum[fm * 2 + 1]);
                    v = tanhfast(av.w + bv1); u = 0.5f * tanhfast(0.5f * (au.w + bu1)) + 0.5f;
                    rowsum[fm * 2 + 1] = fmaf(v * u, w1, rowsum[fm * 2 + 1]);
                }
            }
        }
        __syncthreads();
    }

    #pragma unroll
    for (int o = 1; o <= 2; o <<= 1)
        #pragma unroll
        for (int i = 0; i < 4; i++)
            rowsum[i] += __shfl_xor_sync(0xffffffffu, rowsum[i], o);

    if (tg == 0) {
        #pragma unroll
        for (int i = 0; i < 4; i++)
            red[wn][wm * 32 + (i >> 1) * 16 + (i & 1) * 8 + g] = rowsum[i];
    }
    __syncthreads();
    if (tid < 128) {
        const size_t m = mBase + tid;
        float val = red[0][tid] + red[1][tid] + red[2][tid] + red[3][tid] + bw[0];
        if (mask[m]) val = -1e30f;
        g_logit[m] = val;
    }
}

// ============================================================================
// K3a: per-batch softmax stats (proven).
// ============================================================================
__global__ __launch_bounds__(1024)
void k3a_stats()
{
    __shared__ float sred[1024];
    const int b = blockIdx.x, tid = threadIdx.x;
    const float* lg = g_logit + (size_t)b * TT;

    float lmax = -FLT_MAX;
    #pragma unroll
    for (int i = 0; i < 8; i++) lmax = fmaxf(lmax, lg[tid + i * 1024]);
    sred[tid] = lmax;
    __syncthreads();
    for (int s = 512; s > 0; s >>= 1) {
        if (tid < s) sred[tid] = fmaxf(sred[tid], sred[tid + s]);
        __syncthreads();
    }
    const float mx = sred[0];
    __syncthreads();

    float lsum = 0.f;
    #pragma unroll
    for (int i = 0; i < 8; i++) lsum += __expf(lg[tid + i * 1024] - mx);
    sred[tid] = lsum;
    __syncthreads();
    for (int s = 512; s > 0; s >>= 1) {
        if (tid < s) sred[tid] += sred[tid + s];
        __syncthreads();
    }
    if (tid == 0) g_stat[b] = make_float2(mx, 1.f / sred[0]);
}

// ============================================================================
// K3b: partial pooling from blocked bf16 g_hb4 (proven). grid (64, 8) x 256.
// ============================================================================
#define K3B_LDH 132
#define K3B_SMEM (128 * K3B_LDH * 4)   // 67584 B
__global__ __launch_bounds__(256)
void k3b_pool()
{
    extern __shared__ uint32_t sh[];
    __shared__ float w[128];
    __shared__ float prt[256];
    const int b = blockIdx.y, ch = blockIdx.x, tid = threadIdx.x;
    const char* src = (const char*)g_hb4 + (size_t)(b * 64 + ch) * 65536;
    const uint32_t sbase = s2u(sh);

    #pragma unroll
    for (int j = 0; j < 16; j++) {
        const int c = j * 256 + tid;                   // 4096 uint4 chunks
        const int kp = c >> 5, mw = (c & 31) << 2;
        cpa16(sbase + (kp * K3B_LDH + mw) * 4, src + (size_t)c * 16);
    }
    cp_commit();

    const float2 st = g_stat[b];
    if (tid < 128)
        w[tid] = __expf(g_logit[(size_t)b * TT + ch * 128 + tid] - st.x) * st.y;
    cp_wait0();
    __syncthreads();

    const int kp = tid & 127, mh = tid >> 7;
    const uint32_t* row = sh + kp * K3B_LDH + mh * 64;
    const float* wp = &w[mh * 64];
    float alo = 0.f, ahi = 0.f;
    #pragma unroll
    for (int j = 0; j < 16; j++) {
        const uint4 u = *(const uint4*)(row + j * 4);
        const float w0 = wp[j * 4 + 0], w1 = wp[j * 4 + 1];
        const float w2 = wp[j * 4 + 2], w3 = wp[j * 4 + 3];
        alo = fmaf(w0, __uint_as_float(u.x << 16), alo);
        ahi = fmaf(w0, __uint_as_float(u.x & 0xFFFF0000u), ahi);
        alo = fmaf(w1, __uint_as_float(u.y << 16), alo);
        ahi = fmaf(w1, __uint_as_float(u.y & 0xFFFF0000u), ahi);
        alo = fmaf(w2, __uint_as_float(u.z << 16), alo);
        ahi = fmaf(w2, __uint_as_float(u.z & 0xFFFF0000u), ahi);
        alo = fmaf(w3, __uint_as_float(u.w << 16), alo);
        ahi = fmaf(w3, __uint_as_float(u.w & 0xFFFF0000u), ahi);
    }
    if (mh == 1) { prt[kp * 2] = alo; prt[kp * 2 + 1] = ahi; }
    __syncthreads();
    if (mh == 0) {
        float* dst = &g_part[((size_t)b * 64 + ch) * 256 + kp * 2];
        dst[0] = alo + prt[kp * 2];
        dst[1] = ahi + prt[kp * 2 + 1];
    }
}

// ============================================================================
// k3c_final: reduce 64 partials -> slide -> output logits (proven). grid = 8.
// ============================================================================
__global__ __launch_bounds__(256)
void k3c_final(const float* __restrict__ Wc, const float* __restrict__ bc,
               float* __restrict__ out)
{
    __shared__ float sred[256];
    const int b = blockIdx.x, tid = threadIdx.x;
    float s = 0.f;
    #pragma unroll 8
    for (int j = 0; j < 64; j++) s += g_part[((size_t)b * 64 + j) * 256 + tid];
    sred[tid] = s;
    __syncthreads();
    const int wid = tid >> 5, lane = tid & 31;
    if (wid < 2) {
        float d = 0.f;
        for (int c = lane; c < 256; c += 32) d = fmaf(sred[c], Wc[c * OO + wid], d);
        #pragma unroll
        for (int off = 16; off > 0; off >>= 1) d += __shfl_down_sync(0xffffffffu, d, off);
        if (lane == 0) out[b * OO + wid] = d + bc[wid];
    }
}

// ============================================================================
extern "C" void kernel_launch(void* const* d_in, const int* in_sizes, int n_in,
                              void* d_out, int out_size)
{
    const float*         bags = (const float*)d_in[0];
    const unsigned char* mask = (const unsigned char*)d_in[1];
    const float*         W1   = (const float*)d_in[2];
    const float*         b1   = (const float*)d_in[3];
    const float*         Wv   = (const float*)d_in[4];
    const float*         bv   = (const float*)d_in[5];
    const float*         Wu   = (const float*)d_in[6];
    const float*         bu   = (const float*)d_in[7];
    const float*         ww   = (const float*)d_in[8];
    const float*         bw   = (const float*)d_in[9];
    const float*         Wc   = (const float*)d_in[10];
    const float*         bc   = (const float*)d_in[11];
    float*               out  = (float*)d_out;

    cudaFuncSetAttribute(k12_fused, cudaFuncAttributeMaxDynamicSharedMemorySize, F_SMEM);
    cudaFuncSetAttribute(k3b_pool,  cudaFuncAttributeMaxDynamicSharedMemorySize, K3B_SMEM);

    kpre<<<80, 256>>>(W1, Wv, Wu);
    k12_fused<<<MTOK / 128, 512, F_SMEM>>>(bags, b1, bv, bu, ww, bw, mask);
    k3a_stats<<<BSZ, 1024>>>();
    k3b_pool<<<dim3(NCHUNK, BSZ), 256, K3B_SMEM>>>();
    k3c_final<<<BSZ, 256>>>(Wc, bc, out);
}

// round 15
// speedup vs baseline: 1.0189x; 1.0189x over previous
#include <cuda_runtime.h>
#include <math.h>
#include <stdint.h>
#include <float.h>

#define BSZ 8
#define TT  8192
#define FF  1024
#define HH  256
#define OO  2
#define MTOK (BSZ * TT)   // 65536 tokens

// ---- scratch (static device globals; no runtime allocation) ----
__device__ uint4  g_hb4[(size_t)MTOK * 32];   // 32 MB bf16 h, layout [mblk 512][kp 128][m 128]
__device__ float  g_logit[MTOK];
__device__ float2 g_stat[BSZ];
__device__ float  g_part[BSZ * 128 * HH];     // 1 MB partial pools
__device__ uint4  g_w1s[64 * 512];            // 512 KB: W1 bf16 [kt 64][kp 8][n 256]
__device__ uint4  g_wvs[16 * 512];            // 128 KB: Wv bf16 [blk=nb*4+kh][kp 32][n 64]
__device__ uint4  g_wus[16 * 512];            // 128 KB: Wu

// ---- helpers ----
__device__ __forceinline__ uint32_t pbf(float lo, float hi) {
    uint32_t r; asm("cvt.rn.bf16x2.f32 %0, %1, %2;" : "=r"(r) : "f"(hi), "f"(lo)); return r;
}
__device__ __forceinline__ float tanhfast(float x) {
    float y; asm("tanh.approx.f32 %0, %1;" : "=f"(y) : "f"(x)); return y;
}
__device__ __forceinline__ void mma16(float4& d, const uint32_t* a, uint32_t b0, uint32_t b1) {
    asm volatile("mma.sync.aligned.m16n8k16.row.col.f32.bf16.bf16.f32 "
        "{%0,%1,%2,%3}, {%4,%5,%6,%7}, {%8,%9}, {%0,%1,%2,%3};"
        : "+f"(d.x), "+f"(d.y), "+f"(d.z), "+f"(d.w)
        : "r"(a[0]), "r"(a[1]), "r"(a[2]), "r"(a[3]), "r"(b0), "r"(b1));
}
__device__ __forceinline__ uint32_t s2u(const void* p) {
    uint32_t a; asm("{ .reg .u64 t; cvta.to.shared.u64 t, %1; cvt.u32.u64 %0, t; }" : "=r"(a) : "l"(p));
    return a;
}
__device__ __forceinline__ void cpa16(uint32_t dst, const void* src) {
    asm volatile("cp.async.cg.shared.global [%0], [%1], 16;" :: "r"(dst), "l"(src));
}
__device__ __forceinline__ void cp_commit() { asm volatile("cp.async.commit_group;"); }
__device__ __forceinline__ void cp_wait0()  { asm volatile("cp.async.wait_group 0;"); }
__device__ __forceinline__ void cp_wait1()  { asm volatile("cp.async.wait_group 1;"); }

// ============================================================================
// kpre: merged weight pre-conversion (proven).
// ============================================================================
__global__ __launch_bounds__(256)
void kpre(const float* __restrict__ W1, const float* __restrict__ Wv,
          const float* __restrict__ Wu)
{
    const int tid = threadIdx.x;
    if (blockIdx.x < 64) {
        const int kt = blockIdx.x;
        const int kp = tid >> 5, n8 = (tid & 31) << 3;
        const float* r0 = W1 + (size_t)(kt * 16 + 2 * kp) * HH + n8;
        const float4 a0 = *(const float4*)(r0),        a1 = *(const float4*)(r0 + 4);
        const float4 b0 = *(const float4*)(r0 + HH),   b1 = *(const float4*)(r0 + HH + 4);
        g_w1s[kt * 512 + kp * 64 + (n8 >> 2)] =
            make_uint4(pbf(a0.x, b0.x), pbf(a0.y, b0.y), pbf(a0.z, b0.z), pbf(a0.w, b0.w));
        g_w1s[kt * 512 + kp * 64 + (n8 >> 2) + 1] =
            make_uint4(pbf(a1.x, b1.x), pbf(a1.y, b1.y), pbf(a1.z, b1.z), pbf(a1.w, b1.w));
    } else {
        const int blk = blockIdx.x - 64;
        const int nb = blk >> 2, kh = blk & 3;
        const int kp = tid >> 3, n8 = (tid & 7) << 3;
        const size_t off = (size_t)(kh * 64 + 2 * kp) * HH + nb * 64 + n8;
        {
            const float4 a0 = *(const float4*)(Wv + off),      a1 = *(const float4*)(Wv + off + 4);
            const float4 b0 = *(const float4*)(Wv + off + HH), b1 = *(const float4*)(Wv + off + HH + 4);
            g_wvs[blk * 512 + kp * 16 + (n8 >> 2)] =
                make_uint4(pbf(a0.x, b0.x), pbf(a0.y, b0.y), pbf(a0.z, b0.z), pbf(a0.w, b0.w));
            g_wvs[blk * 512 + kp * 16 + (n8 >> 2) + 1] =
                make_uint4(pbf(a1.x, b1.x), pbf(a1.y, b1.y), pbf(a1.z, b1.z), pbf(a1.w, b1.w));
        }
        {
            const float4 a0 = *(const float4*)(Wu + off),      a1 = *(const float4*)(Wu + off + 4);
            const float4 b0 = *(const float4*)(Wu + off + HH), b1 = *(const float4*)(Wu + off + HH + 4);
            g_wus[blk * 512 + kp * 16 + (n8 >> 2)] =
                make_uint4(pbf(a0.x, b0.x), pbf(a0.y, b0.y), pbf(a0.z, b0.z), pbf(a0.w, b0.w));
            g_wus[blk * 512 + kp * 16 + (n8 >> 2) + 1] =
                make_uint4(pbf(a1.x, b1.x), pbf(a1.y, b1.y), pbf(a1.z, b1.z), pbf(a1.w, b1.w));
        }
    }
}

// ============================================================================
// K12: FUSED h-GEMM + gates. CTA = 64 tokens, 256 thr, 2 CTAs/SM (grid 1024).
// Phase 1 (R13-proven): h = relu(bags@W1+b1), K=32 stages, 3-slot cp.async.
// Phase 2: dual gates GEMM, A resident in smem [kp 128][72], B double-buffered
// [kp 32][136] (8 stages = 2 col-passes x 4 k-quarters). Logits -> g_logit.
// ============================================================================
#define K1_ASLOT (64 * 36)      // 2304 raw A words / slot
#define K1_BSLOT (16 * 264)     // 4224 B words / slot
#define K1_FBUF  (16 * 72)      // 1152 bf16 A words / buffer
#define P2_BSLOT (32 * 136)     // 4352 words per phase-2 B stage
#define F_WORDS  (9216 + 4 * P2_BSLOT)          // 26624 words (phase-2 is larger)
#define F_SMEM   (F_WORDS * 4)                  // 106496 B
__global__ __launch_bounds__(256, 2)
void k12_fused(const float* __restrict__ A, const float* __restrict__ bias,
               const float* __restrict__ bv, const float* __restrict__ bu,
               const float* __restrict__ ww, const float* __restrict__ bw,
               const unsigned char* __restrict__ mask)
{
    extern __shared__ uint32_t sm1[];
    // phase-1 layout (21888 words)
    uint32_t* Araw = sm1;                       // [3][64][36]
    uint32_t* Bst  = sm1 + 3 * K1_ASLOT;        // [3][16][264]
    uint32_t* bfA  = Bst + 3 * K1_BSLOT;        // [2][16][72]
    // phase-2 layout (26624 words, reused post-sync)
    uint32_t* As2  = sm1;                       // [128 kp][72]
    uint32_t* BV2  = sm1 + 9216;                // [2][32][136]
    uint32_t* BU2  = BV2 + 2 * P2_BSLOT;
    __shared__ float red[4][64];
    const uint32_t sAraw = s2u(Araw), sBst = s2u(Bst);
    const uint32_t sBV2 = s2u(BV2), sBU2 = s2u(BU2);

    const int tid = threadIdx.x;
    const int lane = tid & 31, wid = tid >> 5;
    const int wm = wid & 1, wn = wid >> 1;       // both phases: 2 m-warps x 4 n-warps
    const int g = lane >> 2, tg = lane & 3;
    const size_t mBase = (size_t)blockIdx.x * 64;

    // ---------------- phase 1 (R13-proven) ----------------
    const int ar = tid >> 2, aq = tid & 3;       // A: row 0..63, 8k-quarter
    const float* aSrc = A + (mBase + ar) * FF + aq * 8;

    auto issue = [&](int kt2) {
        const int slot = kt2 - (kt2 / 3) * 3;
        const uint32_t aw = sAraw + (slot * K1_ASLOT + ar * 36 + aq * 8) * 4;
        cpa16(aw,      aSrc + kt2 * 32);
        cpa16(aw + 16, aSrc + kt2 * 32 + 4);
        #pragma unroll
        for (int j = 0; j < 2; j++) {
            const int c = tid * 2 + j;
            const int row = c >> 6, col = (c & 63) << 2;
            cpa16(sBst + (slot * K1_BSLOT + row * 264 + col) * 4,
                  (const char*)g_w1s + (size_t)(2 * kt2) * 8192 + (size_t)c * 16);
            cpa16(sBst + (slot * K1_BSLOT + (8 + row) * 264 + col) * 4,
                  (const char*)g_w1s + (size_t)(2 * kt2 + 1) * 8192 + (size_t)c * 16);
        }
        cp_commit();
    };
    issue(0); issue(1);

    float4 acc[2][8];
    #pragma unroll
    for (int i = 0; i < 2; i++)
        #pragma unroll
        for (int j = 0; j < 8; j++) acc[i][j] = make_float4(0.f, 0.f, 0.f, 0.f);

    for (int kt2 = 0; kt2 < 32; kt2++) {
        if (kt2 < 31) cp_wait1();
        else cp_wait0();

        const int slot = kt2 - (kt2 / 3) * 3;
        {
            const uint32_t* rw = Araw + slot * K1_ASLOT + ar * 36 + aq * 8;
            const float4 v0 = *(const float4*)rw;
            const float4 v1 = *(const float4*)(rw + 4);
            uint32_t* bf = bfA + (kt2 & 1) * K1_FBUF;
            bf[(aq * 4 + 0) * 72 + ar] = pbf(v0.x, v0.y);
            bf[(aq * 4 + 1) * 72 + ar] = pbf(v0.z, v0.w);
            bf[(aq * 4 + 2) * 72 + ar] = pbf(v1.x, v1.y);
            bf[(aq * 4 + 3) * 72 + ar] = pbf(v1.z, v1.w);
        }
        __syncthreads();     // publish stage; proves slot (kt2-1)%3 drained
        if (kt2 + 2 < 32) issue(kt2 + 2);

        const uint32_t* ap = bfA + (kt2 & 1) * K1_FBUF;
        const uint32_t* bp = Bst + slot * K1_BSLOT;
        #pragma unroll
        for (int s = 0; s < 2; s++) {
            const int r0 = s * 8 + tg, r1 = s * 8 + tg + 4;
            uint32_t afr[2][4];
            #pragma unroll
            for (int fm = 0; fm < 2; fm++) {
                const int m = wm * 32 + fm * 16 + g;
                afr[fm][0] = ap[r0 * 72 + m];  afr[fm][1] = ap[r0 * 72 + m + 8];
                afr[fm][2] = ap[r1 * 72 + m];  afr[fm][3] = ap[r1 * 72 + m + 8];
            }
            #pragma unroll
            for (int fn = 0; fn < 8; fn++) {
                const int n = wn * 64 + fn * 8 + g;
                const uint32_t b0 = bp[r0 * 264 + n], b1 = bp[r1 * 264 + n];
                mma16(acc[0][fn], afr[0], b0, b1);
                mma16(acc[1][fn], afr[1], b0, b1);
            }
        }
    }
    __syncthreads();   // all phase-1 smem reads done before reuse

    // ---- phase-2 stage-0 B prefetch (hidden under epilogue ALU) ----
    auto fill2 = [&](int s2, int pb) {
        const int pass = s2 >> 2, kh = s2 & 3;
        #pragma unroll
        for (int j = 0; j < 2; j++) {
            const int cc = tid * 2 + j;               // 0..511 chunks per blk
            const int kp = cc >> 4, nw = (cc & 15) * 4;
            #pragma unroll
            for (int q = 0; q < 2; q++) {
                const int blk = (2 * pass + q) * 4 + kh;
                const uint32_t d = (pb * P2_BSLOT + kp * 136 + q * 64 + nw) * 4;
                cpa16(sBV2 + d, (const char*)g_wvs + (size_t)blk * 8192 + (size_t)cc * 16);
                cpa16(sBU2 + d, (const char*)g_wus + (size_t)blk * 8192 + (size_t)cc * 16);
            }
        }
        cp_commit();
    };
    fill2(0, 0);

    // ---- phase-1 epilogue: bias+relu -> As2 [kp][72] + blocked g_hb4 ----
    uint32_t* hbw = (uint32_t*)g_hb4 + (size_t)(blockIdx.x >> 1) * 16384;
    const int mOff = (blockIdx.x & 1) * 64;
    #pragma unroll
    for (int fm = 0; fm < 2; fm++) {
        #pragma unroll
        for (int half = 0; half < 2; half++) {
            const int mloc = wm * 32 + fm * 16 + g + half * 8;
            #pragma unroll
            for (int fn = 0; fn < 8; fn++) {
                const int c = wn * 64 + fn * 8 + tg * 2;
                const float v0 = half ? acc[fm][fn].z : acc[fm][fn].x;
                const float v1 = half ? acc[fm][fn].w : acc[fm][fn].y;
                const float h0 = fmaxf(v0 + bias[c], 0.f);
                const float h1 = fmaxf(v1 + bias[c + 1], 0.f);
                const uint32_t hw = pbf(h0, h1);
                As2[(c >> 1) * 72 + mloc] = hw;
                hbw[(c >> 1) * 128 + mOff + mloc] = hw;
            }
        }
    }
    __syncthreads();   // As2 complete before phase-2 MMAs

    // ---------------- phase 2: gated-attention logits ----------------
    float rowsum[4] = {0.f, 0.f, 0.f, 0.f};
    float4 accV[2][4], accU[2][4];

    for (int s2 = 0; s2 < 8; s2++) {
        const int pb = s2 & 1, pass = s2 >> 2, kh = s2 & 3;
        if (s2 < 7) { fill2(s2 + 1, pb ^ 1); cp_wait1(); }
        else cp_wait0();
        __syncthreads();

        if (kh == 0) {
            #pragma unroll
            for (int i = 0; i < 2; i++)
                #pragma unroll
                for (int j = 0; j < 4; j++) {
                    accV[i][j] = make_float4(0.f, 0.f, 0.f, 0.f);
                    accU[i][j] = make_float4(0.f, 0.f, 0.f, 0.f);
                }
        }

        const uint32_t* vp = BV2 + pb * P2_BSLOT;
        const uint32_t* up = BU2 + pb * P2_BSLOT;
        #pragma unroll
        for (int ks = 0; ks < 4; ks++) {
            const int r = ks * 8 + tg;
            const int ra = kh * 32 + r;
            uint32_t afr[2][4];
            #pragma unroll
            for (int fm = 0; fm < 2; fm++) {
                const int m = wm * 32 + fm * 16 + g;
                afr[fm][0] = As2[ra * 72 + m];       afr[fm][1] = As2[ra * 72 + m + 8];
                afr[fm][2] = As2[(ra + 4) * 72 + m]; afr[fm][3] = As2[(ra + 4) * 72 + m + 8];
            }
            #pragma unroll
            for (int fn = 0; fn < 4; fn++) {
                const int n = wn * 32 + fn * 8 + g;
                const uint32_t v0 = vp[r * 136 + n], v1 = vp[(r + 4) * 136 + n];
                const uint32_t u0 = up[r * 136 + n], u1 = up[(r + 4) * 136 + n];
                mma16(accV[0][fn], afr[0], v0, v1);
                mma16(accV[1][fn], afr[1], v0, v1);
                mma16(accU[0][fn], afr[0], u0, u1);
                mma16(accU[1][fn], afr[1], u0, u1);
            }
        }

        if (kh == 3) {
            #pragma unroll
            for (int fm = 0; fm < 2; fm++) {
                #pragma unroll
                for (int fn = 0; fn < 4; fn++) {
                    const int c = pass * 128 + wn * 32 + fn * 8 + tg * 2;
                    const float bv0 = bv[c], bv1 = bv[c + 1];
                    const float bu0 = bu[c], bu1 = bu[c + 1];
                    const float w0 = ww[c],  w1 = ww[c + 1];
                    const float4 av = accV[fm][fn], au = accU[fm][fn];
                    float v, u;
                    v = tanhfast(av.x + bv0); u = 0.5f * tanhfast(0.5f * (au.x + bu0)) + 0.5f;
                    rowsum[fm * 2 + 0] = fmaf(v * u, w0, rowsum[fm * 2 + 0]);
                    v = tanhfast(av.y + bv1); u = 0.5f * tanhfast(0.5f * (au.y + bu1)) + 0.5f;
                    rowsum[fm * 2 + 0] = fmaf(v * u, w1, rowsum[fm * 2 + 0]);
                    v = tanhfast(av.z + bv0); u = 0.5f * tanhfast(0.5f * (au.z + bu0)) + 0.5f;
                    rowsum[fm * 2 + 1] = fmaf(v * u, w0, rowsum[fm * 2 + 1]);
                    v = tanhfast(av.w + bv1); u = 0.5f * tanhfast(0.5f * (au.w + bu1)) + 0.5f;
                    rowsum[fm * 2 + 1] = fmaf(v * u, w1, rowsum[fm * 2 + 1]);
                }
            }
        }
        __syncthreads();
    }

    #pragma unroll
    for (int o = 1; o <= 2; o <<= 1)
        #pragma unroll
        for (int i = 0; i < 4; i++)
            rowsum[i] += __shfl_xor_sync(0xffffffffu, rowsum[i], o);

    if (tg == 0) {
        #pragma unroll
        for (int i = 0; i < 4; i++)
            red[wn][wm * 32 + (i >> 1) * 16 + (i & 1) * 8 + g] = rowsum[i];
    }
    __syncthreads();
    if (tid < 64) {
        const size_t m = mBase + tid;
        float val = red[0][tid] + red[1][tid] + red[2][tid] + red[3][tid] + bw[0];
        if (mask[m]) val = -1e30f;
        g_logit[m] = val;
    }
}

// ============================================================================
// K3a: per-batch softmax stats (proven).
// ============================================================================
__global__ __launch_bounds__(1024)
void k3a_stats()
{
    __shared__ float sred[1024];
    const int b = blockIdx.x, tid = threadIdx.x;
    const float* lg = g_logit + (size_t)b * TT;

    float lmax = -FLT_MAX;
    #pragma unroll
    for (int i = 0; i < 8; i++) lmax = fmaxf(lmax, lg[tid + i * 1024]);
    sred[tid] = lmax;
    __syncthreads();
    for (int s = 512; s > 0; s >>= 1) {
        if (tid < s) sred[tid] = fmaxf(sred[tid], sred[tid + s]);
        __syncthreads();
    }
    const float mx = sred[0];
    __syncthreads();

    float lsum = 0.f;
    #pragma unroll
    for (int i = 0; i < 8; i++) lsum += __expf(lg[tid + i * 1024] - mx);
    sred[tid] = lsum;
    __syncthreads();
    for (int s = 512; s > 0; s >>= 1) {
        if (tid < s) sred[tid] += sred[tid + s];
        __syncthreads();
    }
    if (tid == 0) g_stat[b] = make_float2(mx, 1.f / sred[0]);
}

// ============================================================================
// K3b: partial pooling from blocked bf16 g_hb4. grid (128 chunks, 8) x 256,
// 64 tokens per chunk, smem tile [kp 128][68].
// ============================================================================
#define K3B_LDH 68
#define K3B_SMEM (128 * K3B_LDH * 4)   // 34816 B
__global__ __launch_bounds__(256)
void k3b_pool()
{
    extern __shared__ uint32_t sh[];
    __shared__ float w[64];
    __shared__ float prt[256];
    const int b = blockIdx.y, ch = blockIdx.x, tid = threadIdx.x;
    const int mblk = b * 64 + (ch >> 1);          // global 128-token block
    const int half = ch & 1;
    const char* src = (const char*)g_hb4 + (size_t)mblk * 65536 + half * 256;
    const uint32_t sbase = s2u(sh);

    // 2048 uint4 chunks: [kp 128][16 m-quads of this half]
    #pragma unroll
    for (int j = 0; j < 8; j++) {
        const int c = j * 256 + tid;
        const int kp = c >> 4, mw = (c & 15) << 2;
        cpa16(sbase + (kp * K3B_LDH + mw) * 4, src + (size_t)kp * 512 + (size_t)mw * 4);
    }
    cp_commit();

    const float2 st = g_stat[b];
    if (tid < 64)
        w[tid] = __expf(g_logit[(size_t)b * TT + ch * 64 + tid] - st.x) * st.y;
    cp_wait0();
    __syncthreads();

    const int kp = tid & 127, mh = tid >> 7;      // col-pair, token-half (32 each)
    const uint32_t* row = sh + kp * K3B_LDH + mh * 32;
    const float* wp = &w[mh * 32];
    float alo = 0.f, ahi = 0.f;
    #pragma unroll
    for (int j = 0; j < 8; j++) {
        const uint4 u = *(const uint4*)(row + j * 4);
        const float w0 = wp[j * 4 + 0], w1 = wp[j * 4 + 1];
        const float w2 = wp[j * 4 + 2], w3 = wp[j * 4 + 3];
        alo = fmaf(w0, __uint_as_float(u.x << 16), alo);
        ahi = fmaf(w0, __uint_as_float(u.x & 0xFFFF0000u), ahi);
        alo = fmaf(w1, __uint_as_float(u.y << 16), alo);
        ahi = fmaf(w1, __uint_as_float(u.y & 0xFFFF0000u), ahi);
        alo = fmaf(w2, __uint_as_float(u.z << 16), alo);
        ahi = fmaf(w2, __uint_as_float(u.z & 0xFFFF0000u), ahi);
        alo = fmaf(w3, __uint_as_float(u.w << 16), alo);
        ahi = fmaf(w3, __uint_as_float(u.w & 0xFFFF0000u), ahi);
    }
    if (mh == 1) { prt[kp * 2] = alo; prt[kp * 2 + 1] = ahi; }
    __syncthreads();
    if (mh == 0) {
        float* dst = &g_part[((size_t)b * 128 + ch) * 256 + kp * 2];
        dst[0] = alo + prt[kp * 2];
        dst[1] = ahi + prt[kp * 2 + 1];
    }
}

// ============================================================================
// k3c_final: reduce 128 partials -> slide -> output logits. grid = 8.
// ============================================================================
__global__ __launch_bounds__(256)
void k3c_final(const float* __restrict__ Wc, const float* __restrict__ bc,
               float* __restrict__ out)
{
    __shared__ float sred[256];
    const int b = blockIdx.x, tid = threadIdx.x;
    float s = 0.f;
    #pragma unroll 8
    for (int j = 0; j < 128; j++) s += g_part[((size_t)b * 128 + j) * 256 + tid];
    sred[tid] = s;
    __syncthreads();
    const int wid = tid >> 5, lane = tid & 31;
    if (wid < 2) {
        float d = 0.f;
        for (int c = lane; c < 256; c += 32) d = fmaf(sred[c], Wc[c * OO + wid], d);
        #pragma unroll
        for (int off = 16; off > 0; off >>= 1) d += __shfl_down_sync(0xffffffffu, d, off);
        if (lane == 0) out[b * OO + wid] = d + bc[wid];
    }
}

// ============================================================================
extern "C" void kernel_launch(void* const* d_in, const int* in_sizes, int n_in,
                              void* d_out, int out_size)
{
    const float*         bags = (const float*)d_in[0];
    const unsigned char* mask = (const unsigned char*)d_in[1];
    const float*         W1   = (const float*)d_in[2];
    const float*         b1   = (const float*)d_in[3];
    const float*         Wv   = (const float*)d_in[4];
    const float*         bv   = (const float*)d_in[5];
    const float*         Wu   = (const float*)d_in[6];
    const float*         bu   = (const float*)d_in[7];
    const float*         ww   = (const float*)d_in[8];
    const float*         bw   = (const float*)d_in[9];
    const float*         Wc   = (const float*)d_in[10];
    const float*         bc   = (const float*)d_in[11];
    float*               out  = (float*)d_out;

    cudaFuncSetAttribute(k12_fused, cudaFuncAttributeMaxDynamicSharedMemorySize, F_SMEM);
    cudaFuncSetAttribute(k3b_pool,  cudaFuncAttributeMaxDynamicSharedMemorySize, K3B_SMEM);

    kpre<<<80, 256>>>(W1, Wv, Wu);
    k12_fused<<<MTOK / 64, 256, F_SMEM>>>(bags, b1, bv, bu, ww, bw, mask);
    k3a_stats<<<BSZ, 1024>>>();
    k3b_pool<<<dim3(128, BSZ), 256, K3B_SMEM>>>();
    k3c_final<<<BSZ, 256>>>(Wc, bc, out);
}